// round 8
// baseline (speedup 1.0000x reference)
#include <cuda_runtime.h>

// SidNetLayer: N=50000, E=600000 per signed adjacency, D=128, K=10, C=0.15.
//   new_P = Ap*P + Am*M + 0.15*X
//   new_M = Am*P + Ap*M
// Sign-partitioned merged CSR: each row's segment holds its POSITIVE edges
// first, then its NEGATIVE edges (per-row mid pointer). The diffuse kernel
// runs two clean loops with no per-edge sign select. One warp per row,
// broadcast LDG.64 edge reads, warp-coalesced float4 gathers.

#define NMAX  50000
#define EMAX  600000
#define DD    128
#define DV    32          // D/4 float4 per row
#define KITER 10
#define CREST 0.15f

// ---------------- persistent device scratch --------------------------------
__device__ int  g_cntp[NMAX];     // per-row positive count (zero at entry;
__device__ int  g_cntm[NMAX];     //  scatter_k restores the invariant)
__device__ int  g_start[NMAX];    // exclusive row starts (combined)
__device__ int  g_mid[NMAX];      // start + pos_count
__device__ int  g_curp[NMAX];     // positive cursor (init = start)
__device__ int  g_curm[NMAX];     // negative cursor (init = mid)
__device__ int2 g_cv[2 * EMAX];   // packed {col, val bits}
__device__ float g_PM[2][(size_t)2 * NMAX * DD];  // ping-pong, P then M

// ---------------- CSR build (3 launches) ------------------------------------
__global__ void hist_k(const int* __restrict__ rp, const int* __restrict__ rm, int E) {
    int i = blockIdx.x * blockDim.x + threadIdx.x;
    if (i < E) {
        atomicAdd(&g_cntp[rp[i]], 1);
        atomicAdd(&g_cntm[rm[i]], 1);
    }
}

// Exclusive scan of (cntp+cntm) -> g_start; also writes mid and both cursors.
// Cross-block prefix via brute-force re-sum of preceding counts (negligible).
__global__ void __launch_bounds__(1024)
scan_k(int n) {
    __shared__ int warp_inc[32];
    __shared__ int warp_off[32];
    __shared__ int red[32];
    __shared__ int sprefix;

    int tid  = threadIdx.x;
    int lane = tid & 31;
    int wid  = tid >> 5;
    int gid  = blockIdx.x * 1024 + tid;

    int vp = (gid < n) ? g_cntp[gid] : 0;
    int vm = (gid < n) ? g_cntm[gid] : 0;
    int v = vp + vm;

    int x = v;
#pragma unroll
    for (int o = 1; o < 32; o <<= 1) {
        int y = __shfl_up_sync(0xffffffffu, x, o);
        if (lane >= o) x += y;
    }
    if (lane == 31) warp_inc[wid] = x;

    int ps = 0;
    int lim = blockIdx.x * 1024;
    for (int i = tid; i < lim; i += 1024) ps += g_cntp[i] + g_cntm[i];
#pragma unroll
    for (int o = 16; o > 0; o >>= 1) ps += __shfl_down_sync(0xffffffffu, ps, o);
    if (lane == 0) red[wid] = ps;
    __syncthreads();

    if (tid < 32) {
        int s = warp_inc[tid];
        int t = s;
#pragma unroll
        for (int o = 1; o < 32; o <<= 1) {
            int y = __shfl_up_sync(0xffffffffu, t, o);
            if (tid >= o) t += y;
        }
        warp_off[tid] = t - s;
        int r = red[tid];
#pragma unroll
        for (int o = 16; o > 0; o >>= 1) r += __shfl_down_sync(0xffffffffu, r, o);
        if (tid == 0) sprefix = r;
    }
    __syncthreads();

    if (gid < n) {
        int st = sprefix + warp_off[wid] + (x - v);
        g_start[gid] = st;
        g_mid[gid]   = st + vp;
        g_curp[gid]  = st;
        g_curm[gid]  = st + vp;
    }
}

__global__ void scatter_k(const int* __restrict__ rp, const int* __restrict__ cp,
                          const float* __restrict__ vp,
                          const int* __restrict__ rm, const int* __restrict__ cm,
                          const float* __restrict__ vm, int E, int n) {
    int i = blockIdx.x * blockDim.x + threadIdx.x;
    if (i < n) { g_cntp[i] = 0; g_cntm[i] = 0; }  // restore invariant
    if (i >= E) return;
    int pos = atomicAdd(&g_curp[rp[i]], 1);
    g_cv[pos] = make_int2(cp[i], __float_as_int(vp[i]));
    pos = atomicAdd(&g_curm[rm[i]], 1);
    g_cv[pos] = make_int2(cm[i], __float_as_int(vm[i]));
}

// ---------------- fused diffusion iteration ---------------------------------
// One warp per row. Positive segment: accP += v*P[c], accM += v*M[c].
// Negative segment: accP += v*M[c], accM += v*P[c]. No per-edge selects.
__global__ void __launch_bounds__(128)
diffuse_k(const float4* __restrict__ Ps, const float4* __restrict__ Ms,
          const float4* __restrict__ X4,
          float4* __restrict__ Pd, float4* __restrict__ Md,
          int n, int Etot) {
    int w = (blockIdx.x * blockDim.x + threadIdx.x) >> 5;
    unsigned lane = threadIdx.x & 31;
    if (w >= n) return;

    float4 x = __ldg(&X4[(unsigned)w * DV + lane]);
    float aP0 = CREST * x.x, aP1 = CREST * x.y, aP2 = CREST * x.z, aP3 = CREST * x.w;
    float aM0 = 0.f, aM1 = 0.f, aM2 = 0.f, aM3 = 0.f;

    int s   = g_start[w];
    int mid = g_mid[w];
    int e   = (w + 1 < n) ? g_start[w + 1] : Etot;

    // positive edges: P[c] -> accP, M[c] -> accM
#pragma unroll 4
    for (int j = s; j < mid; j++) {
        int2 cv = __ldg(&g_cv[j]);          // broadcast 8B record, L1-hot
        float vj = __int_as_float(cv.y);
        unsigned off = (unsigned)cv.x * DV + lane;
        float4 a = __ldg(&Ps[off]);
        float4 b = __ldg(&Ms[off]);
        aP0 += vj * a.x; aP1 += vj * a.y; aP2 += vj * a.z; aP3 += vj * a.w;
        aM0 += vj * b.x; aM1 += vj * b.y; aM2 += vj * b.z; aM3 += vj * b.w;
    }
    // negative edges: M[c] -> accP, P[c] -> accM
#pragma unroll 4
    for (int j = mid; j < e; j++) {
        int2 cv = __ldg(&g_cv[j]);
        float vj = __int_as_float(cv.y);
        unsigned off = (unsigned)cv.x * DV + lane;
        float4 a = __ldg(&Ms[off]);
        float4 b = __ldg(&Ps[off]);
        aP0 += vj * a.x; aP1 += vj * a.y; aP2 += vj * a.z; aP3 += vj * a.w;
        aM0 += vj * b.x; aM1 += vj * b.y; aM2 += vj * b.z; aM3 += vj * b.w;
    }

    Pd[(unsigned)w * DV + lane] = make_float4(aP0, aP1, aP2, aP3);
    Md[(unsigned)w * DV + lane] = make_float4(aM0, aM1, aM2, aM3);
}

// ---------------- launch -----------------------------------------------------
extern "C" void kernel_launch(void* const* d_in, const int* in_sizes, int n_in,
                              void* d_out, int out_size) {
    const int*   rp = (const int*)d_in[0];
    const int*   cp = (const int*)d_in[1];
    const float* vp = (const float*)d_in[2];
    const int*   rm = (const int*)d_in[3];
    const int*   cm = (const int*)d_in[4];
    const float* vm = (const float*)d_in[5];
    const float* X  = (const float*)d_in[6];
    const float* M0 = (const float*)d_in[7];

    int E = in_sizes[0];
    int n = in_sizes[6] / DD;
    int Etot = 2 * E;

    hist_k<<<(E + 255) / 256, 256>>>(rp, rm, E);
    scan_k<<<(n + 1023) / 1024, 1024>>>(n);
    scatter_k<<<(E + 255) / 256, 256>>>(rp, cp, vp, rm, cm, vm, E, n);

    float* gPM = nullptr;
    cudaGetSymbolAddress((void**)&gPM, g_PM);

    const float* Ps = X;
    const float* Ms = M0;
    int grid = (n + 3) / 4;   // 4 warps / 128-thread block, 1 warp per row

    for (int it = 0; it < KITER; ++it) {
        float *Pd, *Md;
        if (it == KITER - 1) {
            Pd = (float*)d_out;
            Md = (float*)d_out + (size_t)n * DD;
        } else {
            int b = it & 1;
            float* basep = gPM + (size_t)b * 2 * NMAX * DD;
            Pd = basep;
            Md = basep + (size_t)n * DD;
        }
        diffuse_k<<<grid, 128>>>((const float4*)Ps, (const float4*)Ms,
                                 (const float4*)X, (float4*)Pd, (float4*)Md,
                                 n, Etot);
        Ps = Pd;
        Ms = Md;
    }
}